// round 1
// baseline (speedup 1.0000x reference)
#include <cuda_runtime.h>
#include <math.h>

#define BATCH 16
#define CHAN  256
#define HH    64
#define WW    64
#define HWSZ  4096
#define NHW   65536   // BATCH*HH*WW
#define EPSBN 1e-5f

// ---------------- scratch (device globals; no allocation allowed) ----------------
__device__ float g_t1[BATCH*CHAN*HWSZ];   // conv1 output
__device__ float g_u [BATCH*CHAN*HWSZ];   // conv2 output (pre-bn2)
__device__ float g_v [BATCH*CHAN*HWSZ];   // shortcut conv output (pre-bns)
__device__ float g_w2t [CHAN*CHAN];       // w_conv2 transposed [ci][co]
__device__ float g_wsct[CHAN*CHAN];       // w_sc   transposed [ci][co]
__device__ float g_spatial[BATCH*CHAN];
__device__ float g_mod    [BATCH*CHAN];
// [0:C) sum_t1, [C:2C) sq_t1, [2C:3C) sum_u, [3C:4C) sq_u, [4C:5C) sum_v, [5C:6C) sq_v
__device__ float g_stats[6*CHAN];

__device__ __forceinline__ float sigmoidf_(float z) { return 1.f / (1.f + expf(-z)); }
__device__ __forceinline__ float siluf_(float z)    { return z / (1.f + expf(-z)); }

// ---------------- zero the stats accumulators ----------------
__global__ void k_zero_stats() {
    int i = blockIdx.x * blockDim.x + threadIdx.x;
    if (i < 6*CHAN) g_stats[i] = 0.f;
}

// ---------------- spatial proj: mean over HW of depthwise 3x3 conv(x) ----------------
__global__ void k_spatial(const float* __restrict__ x, const float* __restrict__ w_ch) {
    int bc = blockIdx.x;                 // b*CHAN + c
    int c  = bc & (CHAN-1);
    const float* xp = x + (size_t)bc * HWSZ;
    float wk[9];
#pragma unroll
    for (int i = 0; i < 9; i++) wk[i] = w_ch[c*9 + i];

    float acc = 0.f;
    for (int i = threadIdx.x; i < HWSZ; i += blockDim.x) {
        int h = i >> 6, w = i & 63;
        float s = 0.f;
#pragma unroll
        for (int ky = 0; ky < 3; ky++) {
            int gh = h + ky - 1;
            if (gh < 0 || gh >= HH) continue;
#pragma unroll
            for (int kx = 0; kx < 3; kx++) {
                int gw = w + kx - 1;
                if (gw < 0 || gw >= WW) continue;
                s += wk[ky*3+kx] * xp[gh*WW + gw];
            }
        }
        acc += s;
    }
    __shared__ float red[256];
    red[threadIdx.x] = acc;
    __syncthreads();
    for (int s = 128; s > 0; s >>= 1) {
        if (threadIdx.x < s) red[threadIdx.x] += red[threadIdx.x + s];
        __syncthreads();
    }
    if (threadIdx.x == 0) g_spatial[bc] = red[0] * (1.f / (float)HWSZ);
}

// ---------------- gate MLP -> g_mod ----------------
__global__ void k_mod(const float* __restrict__ dce, const float* __restrict__ w_dce,
                      const float* __restrict__ b_dce, const float* __restrict__ w_sh,
                      const float* __restrict__ b_sh, const float* __restrict__ w_ex,
                      const float* __restrict__ b_ex) {
    int b = blockIdx.x;
    int t = threadIdx.x;                 // 128 threads
    __shared__ float pooled[128];
    __shared__ float mbuf[256];
    __shared__ float hbuf[128];

    // AdaptiveAvgPool1d over L=100
    {
        float s = 0.f;
        const float* dp = dce + (size_t)b * 100 * 128 + t;
        for (int l = 0; l < 100; l++) s += dp[l * 128];
        pooled[t] = s * 0.01f;
    }
    __syncthreads();

    // dce_proj * spatial_proj
    for (int co = t; co < 256; co += 128) {
        float a = b_dce[co];
        const float* wr = w_dce + (size_t)co * 128;
        for (int j = 0; j < 128; j++) a += pooled[j] * wr[j];
        mbuf[co] = a * g_spatial[b*CHAN + co];
    }
    __syncthreads();

    // shrink + relu
    {
        float a = b_sh[t];
        const float* wr = w_sh + (size_t)t * 256;
        for (int i = 0; i < 256; i++) a += mbuf[i] * wr[i];
        hbuf[t] = fmaxf(a, 0.f);
    }
    __syncthreads();

    // expand + sigmoid
    for (int co = t; co < 256; co += 128) {
        float a = b_ex[co];
        const float* wr = w_ex + (size_t)co * 128;
        for (int i = 0; i < 128; i++) a += hbuf[i] * wr[i];
        g_mod[b*CHAN + co] = sigmoidf_(a);
    }
}

// ---------------- transpose 1x1 weights ----------------
__global__ void k_transpose(const float* __restrict__ w2, const float* __restrict__ wsc) {
    int idx = blockIdx.x * blockDim.x + threadIdx.x;    // 65536 total
    if (idx >= CHAN*CHAN) return;
    int co = idx >> 8, ci = idx & 255;
    g_w2t [ci*CHAN + co] = w2 [idx];
    g_wsct[ci*CHAN + co] = wsc[idx];
}

// ---------------- conv1: 3x3, xm = x*mod computed on the fly; also bn1 stats ----------------
// grid: (64 spatial tiles 8x8, 4 cout groups of 64, 16 batches), 256 threads
__global__ void __launch_bounds__(256) k_conv1(const float* __restrict__ x,
                                               const float* __restrict__ w1) {
    int b    = blockIdx.z;
    int co0  = blockIdx.y * 64;
    int tile = blockIdx.x;
    int th0  = (tile >> 3) * 8;
    int tw0  = (tile & 7) * 8;

    __shared__ float s_in[8 * 100];        // 8 cin x 10x10 patch
    __shared__ float s_w [9 * 8 * 64];     // [tap][cin][cout]
    __shared__ float s_sum[64], s_sq[64];

    int tid = threadIdx.x;
    if (tid < 64) { s_sum[tid] = 0.f; s_sq[tid] = 0.f; }

    int co_t = tid & 15;           // cout group
    int sp_t = tid >> 4;           // spatial group
    int py   = sp_t >> 1;
    int px0  = (sp_t & 1) * 4;
    int co_l = co_t * 4;

    float acc[4][4];
#pragma unroll
    for (int k = 0; k < 4; k++)
#pragma unroll
        for (int j = 0; j < 4; j++) acc[k][j] = 0.f;

    const float* modp = g_mod + b*CHAN;

    for (int c0 = 0; c0 < CHAN; c0 += 8) {
        // input patch (with mod applied)
        for (int idx = tid; idx < 800; idx += 256) {
            int ci = idx / 100, r = idx - ci*100;
            int iy = r / 10, ix = r - iy*10;
            int gh = th0 + iy - 1, gw = tw0 + ix - 1;
            float v = 0.f;
            if (gh >= 0 && gh < HH && gw >= 0 && gw < WW)
                v = x[(((size_t)b*CHAN + c0 + ci)*HH + gh)*WW + gw] * modp[c0 + ci];
            s_in[idx] = v;
        }
        // weights, coalesced read, scattered store: s_w[t][ci][co]
        for (int idx = tid; idx < 4608; idx += 256) {
            int co = idx / 72, rem = idx - co*72;   // rem = ci*9 + t
            int ci = rem / 9, t = rem - ci*9;
            s_w[(t*8 + ci)*64 + co] = w1[(size_t)(co0+co)*2304 + (size_t)c0*9 + rem];
            (void)ci;
        }
        __syncthreads();

#pragma unroll
        for (int ci = 0; ci < 8; ci++) {
#pragma unroll
            for (int t = 0; t < 9; t++) {
                int ky = t / 3, kx = t - ky*3;
                const float* ip = &s_in[ci*100 + (py + ky)*10 + px0 + kx];
                float4 wv = *(const float4*)&s_w[(t*8 + ci)*64 + co_l];
                float i0 = ip[0], i1 = ip[1], i2 = ip[2], i3 = ip[3];
                acc[0][0] += i0*wv.x; acc[0][1] += i0*wv.y; acc[0][2] += i0*wv.z; acc[0][3] += i0*wv.w;
                acc[1][0] += i1*wv.x; acc[1][1] += i1*wv.y; acc[1][2] += i1*wv.z; acc[1][3] += i1*wv.w;
                acc[2][0] += i2*wv.x; acc[2][1] += i2*wv.y; acc[2][2] += i2*wv.z; acc[2][3] += i2*wv.w;
                acc[3][0] += i3*wv.x; acc[3][1] += i3*wv.y; acc[3][2] += i3*wv.z; acc[3][3] += i3*wv.w;
            }
        }
        __syncthreads();
    }

    // store + bn1 partial stats
#pragma unroll
    for (int j = 0; j < 4; j++) {
        float ls = 0.f, lq = 0.f;
#pragma unroll
        for (int k = 0; k < 4; k++) { float v = acc[k][j]; ls += v; lq += v*v; }
        atomicAdd(&s_sum[co_l + j], ls);
        atomicAdd(&s_sq [co_l + j], lq);
        float4 vv = make_float4(acc[0][j], acc[1][j], acc[2][j], acc[3][j]);
        size_t o = (((size_t)b*CHAN + co0 + co_l + j)*HH + th0 + py)*WW + tw0 + px0;
        *(float4*)&g_t1[o] = vv;
    }
    __syncthreads();
    if (tid < 64) {
        atomicAdd(&g_stats[co0 + tid],        s_sum[tid]);
        atomicAdd(&g_stats[CHAN + co0 + tid], s_sq[tid]);
    }
}

// ---------------- fused dual 1x1 GEMM: u = w2 @ silu(bn1(t1)), v = wsc @ (x*mod) ----------------
// grid: (B*H = 1024, 4 cout groups), 256 threads; block = one (b,h) row of 64 pixels x 64 couts
__global__ void __launch_bounds__(256) k_gemm(const float* __restrict__ x,
                                              const float* __restrict__ g1,
                                              const float* __restrict__ be1) {
    int bh  = blockIdx.x;
    int b   = bh >> 6;
    int h   = bh & 63;
    int co0 = blockIdx.y * 64;
    int tid = threadIdx.x;

    __shared__ float s_scale[CHAN], s_shift[CHAN];
    __shared__ float s_a [16*64];
    __shared__ float s_m [16*64];
    __shared__ float s_w2[16*64];
    __shared__ float s_ws[16*64];
    __shared__ float s_su[64], s_qu[64], s_sv[64], s_qv[64];

    // bn1 affine per channel
    {
        int c = tid;   // 256 threads == 256 channels
        float mean = g_stats[c] * (1.f / (float)NHW);
        float var  = g_stats[CHAN + c] * (1.f / (float)NHW) - mean*mean;
        float sc   = g1[c] * rsqrtf(var + EPSBN);
        s_scale[c] = sc;
        s_shift[c] = be1[c] - mean * sc;
    }
    if (tid < 64) { s_su[tid]=0.f; s_qu[tid]=0.f; s_sv[tid]=0.f; s_qv[tid]=0.f; }
    __syncthreads();

    int co_t = tid & 15;
    int sp_t = tid >> 4;
    int p0   = sp_t * 4;
    int co_l = co_t * 4;

    float au[4][4], av[4][4];
#pragma unroll
    for (int k = 0; k < 4; k++)
#pragma unroll
        for (int j = 0; j < 4; j++) { au[k][j] = 0.f; av[k][j] = 0.f; }

    for (int c0 = 0; c0 < CHAN; c0 += 16) {
        for (int idx = tid; idx < 1024; idx += 256) {
            int ci = idx >> 6, p = idx & 63;
            int cin = c0 + ci;
            size_t gi = (((size_t)b*CHAN + cin)*HH + h)*WW + p;
            float z = fmaf(g_t1[gi], s_scale[cin], s_shift[cin]);
            s_a[idx] = siluf_(z);
            s_m[idx] = x[gi] * g_mod[b*CHAN + cin];
            // weight tiles (transposed layout: [ci][co])
            s_w2[idx] = g_w2t [(size_t)cin*CHAN + co0 + p];
            s_ws[idx] = g_wsct[(size_t)cin*CHAN + co0 + p];
        }
        __syncthreads();

#pragma unroll
        for (int ci = 0; ci < 16; ci++) {
            float4 a4 = *(const float4*)&s_a [ci*64 + p0];
            float4 m4 = *(const float4*)&s_m [ci*64 + p0];
            float4 w4 = *(const float4*)&s_w2[ci*64 + co_l];
            float4 s4 = *(const float4*)&s_ws[ci*64 + co_l];
            float ak[4] = {a4.x, a4.y, a4.z, a4.w};
            float mk[4] = {m4.x, m4.y, m4.z, m4.w};
            float wj[4] = {w4.x, w4.y, w4.z, w4.w};
            float sj[4] = {s4.x, s4.y, s4.z, s4.w};
#pragma unroll
            for (int k = 0; k < 4; k++)
#pragma unroll
                for (int j = 0; j < 4; j++) {
                    au[k][j] += ak[k] * wj[j];
                    av[k][j] += mk[k] * sj[j];
                }
        }
        __syncthreads();
    }

    // store + stats
#pragma unroll
    for (int j = 0; j < 4; j++) {
        float lsu = 0.f, lqu = 0.f, lsv = 0.f, lqv = 0.f;
#pragma unroll
        for (int k = 0; k < 4; k++) {
            float uu = au[k][j], vv = av[k][j];
            lsu += uu; lqu += uu*uu; lsv += vv; lqv += vv*vv;
        }
        atomicAdd(&s_su[co_l + j], lsu);
        atomicAdd(&s_qu[co_l + j], lqu);
        atomicAdd(&s_sv[co_l + j], lsv);
        atomicAdd(&s_qv[co_l + j], lqv);
        size_t o = (((size_t)b*CHAN + co0 + co_l + j)*HH + h)*WW + p0;
        *(float4*)&g_u[o] = make_float4(au[0][j], au[1][j], au[2][j], au[3][j]);
        *(float4*)&g_v[o] = make_float4(av[0][j], av[1][j], av[2][j], av[3][j]);
    }
    __syncthreads();
    if (tid < 64) {
        atomicAdd(&g_stats[2*CHAN + co0 + tid], s_su[tid]);
        atomicAdd(&g_stats[3*CHAN + co0 + tid], s_qu[tid]);
        atomicAdd(&g_stats[4*CHAN + co0 + tid], s_sv[tid]);
        atomicAdd(&g_stats[5*CHAN + co0 + tid], s_qv[tid]);
    }
}

// ---------------- final: out = silu(bn2(u) + bns(v)) ----------------
__global__ void k_final(float* __restrict__ out,
                        const float* __restrict__ g2, const float* __restrict__ be2,
                        const float* __restrict__ gs, const float* __restrict__ bes) {
    int i4 = blockIdx.x * blockDim.x + threadIdx.x;
    size_t base = (size_t)i4 * 4;
    if (base >= (size_t)BATCH*CHAN*HWSZ) return;
    int c = (int)((base >> 12) & 255);

    float mu = g_stats[2*CHAN + c] * (1.f / (float)NHW);
    float vu = g_stats[3*CHAN + c] * (1.f / (float)NHW) - mu*mu;
    float su = g2[c] * rsqrtf(vu + EPSBN);
    float bu = be2[c] - mu * su;

    float mv = g_stats[4*CHAN + c] * (1.f / (float)NHW);
    float vv = g_stats[5*CHAN + c] * (1.f / (float)NHW) - mv*mv;
    float sv = gs[c] * rsqrtf(vv + EPSBN);
    float bv = bes[c] - mv * sv;

    float4 u = *(const float4*)&g_u[base];
    float4 v = *(const float4*)&g_v[base];
    float4 o;
    {
        float z;
        z = fmaf(u.x, su, bu) + fmaf(v.x, sv, bv); o.x = siluf_(z);
        z = fmaf(u.y, su, bu) + fmaf(v.y, sv, bv); o.y = siluf_(z);
        z = fmaf(u.z, su, bu) + fmaf(v.z, sv, bv); o.z = siluf_(z);
        z = fmaf(u.w, su, bu) + fmaf(v.w, sv, bv); o.w = siluf_(z);
    }
    *(float4*)&out[base] = o;
}

// ---------------- launch ----------------
extern "C" void kernel_launch(void* const* d_in, const int* in_sizes, int n_in,
                              void* d_out, int out_size) {
    const float* x        = (const float*)d_in[0];
    const float* dce      = (const float*)d_in[1];
    const float* w_dce    = (const float*)d_in[2];
    const float* b_dce    = (const float*)d_in[3];
    const float* w_ch     = (const float*)d_in[4];
    const float* w_shrink = (const float*)d_in[5];
    const float* b_shrink = (const float*)d_in[6];
    const float* w_expand = (const float*)d_in[7];
    const float* b_expand = (const float*)d_in[8];
    const float* w_conv1  = (const float*)d_in[9];
    const float* g_bn1    = (const float*)d_in[10];
    const float* be_bn1   = (const float*)d_in[11];
    const float* w_conv2  = (const float*)d_in[12];
    const float* g_bn2    = (const float*)d_in[13];
    const float* be_bn2   = (const float*)d_in[14];
    const float* w_sc     = (const float*)d_in[15];
    const float* g_bns    = (const float*)d_in[16];
    const float* be_bns   = (const float*)d_in[17];
    float* out = (float*)d_out;

    k_zero_stats<<<6, 256>>>();
    k_spatial<<<BATCH*CHAN, 256>>>(x, w_ch);
    k_mod<<<BATCH, 128>>>(dce, w_dce, b_dce, w_shrink, b_shrink, w_expand, b_expand);
    k_transpose<<<256, 256>>>(w_conv2, w_sc);
    k_conv1<<<dim3(64, 4, BATCH), 256>>>(x, w_conv1);
    k_gemm<<<dim3(BATCH*HH, 4), 256>>>(x, g_bn1, be_bn1);
    k_final<<<(BATCH*CHAN*HWSZ/4 + 255)/256, 256>>>(out, g_bn2, be_bn2, g_bns, be_bns);
}

// round 2
// speedup vs baseline: 1.5743x; 1.5743x over previous
#include <cuda_runtime.h>
#include <math.h>
#include <stdint.h>

#define BATCH 16
#define CHAN  256
#define HH    64
#define WW    64
#define HWSZ  4096
#define NHW   65536   // BATCH*HH*WW
#define EPSBN 1e-5f

// ---------------- scratch (device globals; no allocation allowed) ----------------
__device__ float g_t1[BATCH*CHAN*HWSZ];   // conv1 output
__device__ float g_u [BATCH*CHAN*HWSZ];   // conv2 output (pre-bn2)
__device__ float g_v [BATCH*CHAN*HWSZ];   // shortcut conv output (pre-bns)
__device__ float g_w2t [CHAN*CHAN];       // w_conv2 transposed [ci][co]
__device__ float g_wsct[CHAN*CHAN];       // w_sc   transposed [ci][co]
__device__ uint32_t g_w1t[9*CHAN*CHAN];   // w_conv1 as tf32 bits, [tap][ci][co]
__device__ float g_spatial[BATCH*CHAN];
__device__ float g_mod    [BATCH*CHAN];
// [0:C) sum_t1, [C:2C) sq_t1, [2C:3C) sum_u, [3C:4C) sq_u, [4C:5C) sum_v, [5C:6C) sq_v
__device__ float g_stats[6*CHAN];

__device__ __forceinline__ float sigmoidf_(float z) { return 1.f / (1.f + expf(-z)); }
__device__ __forceinline__ float siluf_(float z)    { return z / (1.f + expf(-z)); }

__device__ __forceinline__ uint32_t f2tf32(float f) {
    uint32_t u;
    asm("cvt.rna.tf32.f32 %0, %1;" : "=r"(u) : "f"(f));
    return u;
}

__device__ __forceinline__ void mma_tf32(float* c, uint32_t a0, uint32_t a1,
                                         uint32_t a2, uint32_t a3,
                                         uint32_t b0, uint32_t b1) {
    asm volatile(
        "mma.sync.aligned.m16n8k8.row.col.f32.tf32.tf32.f32 "
        "{%0,%1,%2,%3}, {%4,%5,%6,%7}, {%8,%9}, {%0,%1,%2,%3};"
        : "+f"(c[0]), "+f"(c[1]), "+f"(c[2]), "+f"(c[3])
        : "r"(a0), "r"(a1), "r"(a2), "r"(a3), "r"(b0), "r"(b1));
}

// ---------------- zero the stats accumulators ----------------
__global__ void k_zero_stats() {
    int i = blockIdx.x * blockDim.x + threadIdx.x;
    if (i < 6*CHAN) g_stats[i] = 0.f;
}

// ---------------- spatial proj: mean over HW of depthwise 3x3 conv(x) ----------------
__global__ void k_spatial(const float* __restrict__ x, const float* __restrict__ w_ch) {
    int bc = blockIdx.x;                 // b*CHAN + c
    int c  = bc & (CHAN-1);
    const float* xp = x + (size_t)bc * HWSZ;
    float wk[9];
#pragma unroll
    for (int i = 0; i < 9; i++) wk[i] = w_ch[c*9 + i];

    float acc = 0.f;
    for (int i = threadIdx.x; i < HWSZ; i += blockDim.x) {
        int h = i >> 6, w = i & 63;
        float s = 0.f;
#pragma unroll
        for (int ky = 0; ky < 3; ky++) {
            int gh = h + ky - 1;
            if (gh < 0 || gh >= HH) continue;
#pragma unroll
            for (int kx = 0; kx < 3; kx++) {
                int gw = w + kx - 1;
                if (gw < 0 || gw >= WW) continue;
                s += wk[ky*3+kx] * xp[gh*WW + gw];
            }
        }
        acc += s;
    }
    __shared__ float red[256];
    red[threadIdx.x] = acc;
    __syncthreads();
    for (int s = 128; s > 0; s >>= 1) {
        if (threadIdx.x < s) red[threadIdx.x] += red[threadIdx.x + s];
        __syncthreads();
    }
    if (threadIdx.x == 0) g_spatial[bc] = red[0] * (1.f / (float)HWSZ);
}

// ---------------- gate MLP -> g_mod ----------------
__global__ void k_mod(const float* __restrict__ dce, const float* __restrict__ w_dce,
                      const float* __restrict__ b_dce, const float* __restrict__ w_sh,
                      const float* __restrict__ b_sh, const float* __restrict__ w_ex,
                      const float* __restrict__ b_ex) {
    int b = blockIdx.x;
    int t = threadIdx.x;                 // 128 threads
    __shared__ float pooled[128];
    __shared__ float mbuf[256];
    __shared__ float hbuf[128];

    {
        float s = 0.f;
        const float* dp = dce + (size_t)b * 100 * 128 + t;
        for (int l = 0; l < 100; l++) s += dp[l * 128];
        pooled[t] = s * 0.01f;
    }
    __syncthreads();

    for (int co = t; co < 256; co += 128) {
        float a = b_dce[co];
        const float* wr = w_dce + (size_t)co * 128;
        for (int j = 0; j < 128; j++) a += pooled[j] * wr[j];
        mbuf[co] = a * g_spatial[b*CHAN + co];
    }
    __syncthreads();

    {
        float a = b_sh[t];
        const float* wr = w_sh + (size_t)t * 256;
        for (int i = 0; i < 256; i++) a += mbuf[i] * wr[i];
        hbuf[t] = fmaxf(a, 0.f);
    }
    __syncthreads();

    for (int co = t; co < 256; co += 128) {
        float a = b_ex[co];
        const float* wr = w_ex + (size_t)co * 128;
        for (int i = 0; i < 128; i++) a += hbuf[i] * wr[i];
        g_mod[b*CHAN + co] = sigmoidf_(a);
    }
}

// ---------------- transpose 1x1 weights ----------------
__global__ void k_transpose(const float* __restrict__ w2, const float* __restrict__ wsc) {
    int idx = blockIdx.x * blockDim.x + threadIdx.x;    // 65536 total
    if (idx >= CHAN*CHAN) return;
    int co = idx >> 8, ci = idx & 255;
    g_w2t [ci*CHAN + co] = w2 [idx];
    g_wsct[ci*CHAN + co] = wsc[idx];
}

// ---------------- transpose conv1 weights to [tap][ci][co], tf32-rounded ----------------
__global__ void k_w1t(const float* __restrict__ w1) {
    int idx = blockIdx.x * blockDim.x + threadIdx.x;    // 589824 total
    if (idx >= 9*CHAN*CHAN) return;
    int tap = idx >> 16;
    int rem = idx & 65535;
    int ci  = rem >> 8;
    int co  = rem & 255;
    g_w1t[idx] = f2tf32(w1[(size_t)co*2304 + ci*9 + tap]);
}

// ---------------- conv1 via tf32 mma.sync: 9 shifted GEMMs ----------------
// grid: (32 spatial tiles of 16x8, 4 cout groups of 64, 16 batches), 256 threads (8 warps)
// warp w covers pixel rows [w*2, w*2+2) x 8 cols (M=16), all 64 couts (8 n-tiles)
#define PSTR 185
__global__ void __launch_bounds__(256) k_conv1_mma(const float* __restrict__ x) {
    int b    = blockIdx.z;
    int co0  = blockIdx.y * 64;
    int tile = blockIdx.x;
    int th0  = (tile >> 3) * 16;
    int tw0  = (tile & 7) * 8;

    __shared__ uint32_t s_in[16 * PSTR];   // 16 cin x (18x10 halo patch), padded stride
    __shared__ uint32_t s_b [16 * 65];     // [k16][co64+pad]
    __shared__ float s_sum[64], s_sq[64];

    int tid  = threadIdx.x;
    int warp = tid >> 5;
    int lane = tid & 31;
    int gid  = lane >> 2;     // group id 0..7
    int tq   = lane & 3;      // thread-in-group 0..3
    int w2   = warp * 2;      // pixel row base for this warp

    if (tid < 64) { s_sum[tid] = 0.f; s_sq[tid] = 0.f; }

    float acc[8][4];
#pragma unroll
    for (int j = 0; j < 8; j++)
#pragma unroll
        for (int k = 0; k < 4; k++) acc[j][k] = 0.f;

    const float* modp = g_mod + b*CHAN;

    for (int c0 = 0; c0 < CHAN; c0 += 16) {
        __syncthreads();   // protect s_in from previous iteration's mma reads
        // fill input halo patch (mod applied, tf32-rounded)
        for (int idx = tid; idx < 16*180; idx += 256) {
            int ci = idx / 180, r = idx - ci*180;
            int iy = r / 10, ix = r - iy*10;
            int gh = th0 + iy - 1, gw = tw0 + ix - 1;
            float v = 0.f;
            if (gh >= 0 && gh < HH && gw >= 0 && gw < WW)
                v = x[(((size_t)b*CHAN + c0 + ci)*HH + gh)*WW + gw] * modp[c0 + ci];
            s_in[ci*PSTR + iy*10 + ix] = f2tf32(v);
        }

#pragma unroll
        for (int tap = 0; tap < 9; tap++) {
            int ky = tap / 3, kx = tap - ky*3;
            __syncthreads();   // s_b reuse barrier (also covers patch fill at tap 0)
            for (int idx = tid; idx < 1024; idx += 256) {
                int kk = idx >> 6, co = idx & 63;
                s_b[kk*65 + co] = g_w1t[tap*65536 + (c0+kk)*256 + co0 + co];
            }
            __syncthreads();

            int arow = (w2 + ky)*10 + gid + kx;
#pragma unroll
            for (int kk0 = 0; kk0 < 16; kk0 += 8) {
                const uint32_t* ap = s_in + (kk0 + tq)*PSTR + arow;
                uint32_t a0 = ap[0];
                uint32_t a1 = ap[10];
                uint32_t a2 = ap[4*PSTR];
                uint32_t a3 = ap[4*PSTR + 10];
                const uint32_t* bp = s_b + (kk0 + tq)*65 + gid;
#pragma unroll
                for (int j = 0; j < 8; j++) {
                    uint32_t b0 = bp[j*8];
                    uint32_t b1 = bp[j*8 + 4*65];
                    mma_tf32(acc[j], a0, a1, a2, a3, b0, b1);
                }
            }
        }
    }

    // store results + bn1 partial stats
    int py0 = th0 + w2;
    int px  = tw0 + gid;
#pragma unroll
    for (int j = 0; j < 8; j++) {
        int co = co0 + j*8 + tq*2;
        size_t o0 = (((size_t)b*CHAN + co)*HH + py0)*WW + px;
        g_t1[o0]               = acc[j][0];
        g_t1[o0 + HWSZ]        = acc[j][1];   // co+1
        g_t1[o0 + WW]          = acc[j][2];   // row+1
        g_t1[o0 + HWSZ + WW]   = acc[j][3];

        float s0 = acc[j][0] + acc[j][2];
        float s1 = acc[j][1] + acc[j][3];
        float q0 = acc[j][0]*acc[j][0] + acc[j][2]*acc[j][2];
        float q1 = acc[j][1]*acc[j][1] + acc[j][3]*acc[j][3];
#pragma unroll
        for (int o = 4; o < 32; o <<= 1) {
            s0 += __shfl_xor_sync(0xffffffffu, s0, o);
            s1 += __shfl_xor_sync(0xffffffffu, s1, o);
            q0 += __shfl_xor_sync(0xffffffffu, q0, o);
            q1 += __shfl_xor_sync(0xffffffffu, q1, o);
        }
        if (gid == 0) {
            atomicAdd(&s_sum[j*8 + tq*2],     s0);
            atomicAdd(&s_sum[j*8 + tq*2 + 1], s1);
            atomicAdd(&s_sq [j*8 + tq*2],     q0);
            atomicAdd(&s_sq [j*8 + tq*2 + 1], q1);
        }
    }
    __syncthreads();
    if (tid < 64) {
        atomicAdd(&g_stats[co0 + tid],        s_sum[tid]);
        atomicAdd(&g_stats[CHAN + co0 + tid], s_sq[tid]);
    }
}

// ---------------- fused dual 1x1 GEMM: u = w2 @ silu(bn1(t1)), v = wsc @ (x*mod) ----------------
__global__ void __launch_bounds__(256) k_gemm(const float* __restrict__ x,
                                              const float* __restrict__ g1,
                                              const float* __restrict__ be1) {
    int bh  = blockIdx.x;
    int b   = bh >> 6;
    int h   = bh & 63;
    int co0 = blockIdx.y * 64;
    int tid = threadIdx.x;

    __shared__ float s_scale[CHAN], s_shift[CHAN];
    __shared__ float s_a [16*64];
    __shared__ float s_m [16*64];
    __shared__ float s_w2[16*64];
    __shared__ float s_ws[16*64];
    __shared__ float s_su[64], s_qu[64], s_sv[64], s_qv[64];

    {
        int c = tid;
        float mean = g_stats[c] * (1.f / (float)NHW);
        float var  = g_stats[CHAN + c] * (1.f / (float)NHW) - mean*mean;
        float sc   = g1[c] * rsqrtf(var + EPSBN);
        s_scale[c] = sc;
        s_shift[c] = be1[c] - mean * sc;
    }
    if (tid < 64) { s_su[tid]=0.f; s_qu[tid]=0.f; s_sv[tid]=0.f; s_qv[tid]=0.f; }
    __syncthreads();

    int co_t = tid & 15;
    int sp_t = tid >> 4;
    int p0   = sp_t * 4;
    int co_l = co_t * 4;

    float au[4][4], av[4][4];
#pragma unroll
    for (int k = 0; k < 4; k++)
#pragma unroll
        for (int j = 0; j < 4; j++) { au[k][j] = 0.f; av[k][j] = 0.f; }

    for (int c0 = 0; c0 < CHAN; c0 += 16) {
        for (int idx = tid; idx < 1024; idx += 256) {
            int ci = idx >> 6, p = idx & 63;
            int cin = c0 + ci;
            size_t gi = (((size_t)b*CHAN + cin)*HH + h)*WW + p;
            float z = fmaf(g_t1[gi], s_scale[cin], s_shift[cin]);
            s_a[idx] = siluf_(z);
            s_m[idx] = x[gi] * g_mod[b*CHAN + cin];
            s_w2[idx] = g_w2t [(size_t)cin*CHAN + co0 + p];
            s_ws[idx] = g_wsct[(size_t)cin*CHAN + co0 + p];
        }
        __syncthreads();

#pragma unroll
        for (int ci = 0; ci < 16; ci++) {
            float4 a4 = *(const float4*)&s_a [ci*64 + p0];
            float4 m4 = *(const float4*)&s_m [ci*64 + p0];
            float4 w4 = *(const float4*)&s_w2[ci*64 + co_l];
            float4 s4 = *(const float4*)&s_ws[ci*64 + co_l];
            float ak[4] = {a4.x, a4.y, a4.z, a4.w};
            float mk[4] = {m4.x, m4.y, m4.z, m4.w};
            float wj[4] = {w4.x, w4.y, w4.z, w4.w};
            float sj[4] = {s4.x, s4.y, s4.z, s4.w};
#pragma unroll
            for (int k = 0; k < 4; k++)
#pragma unroll
                for (int j = 0; j < 4; j++) {
                    au[k][j] += ak[k] * wj[j];
                    av[k][j] += mk[k] * sj[j];
                }
        }
        __syncthreads();
    }

#pragma unroll
    for (int j = 0; j < 4; j++) {
        float lsu = 0.f, lqu = 0.f, lsv = 0.f, lqv = 0.f;
#pragma unroll
        for (int k = 0; k < 4; k++) {
            float uu = au[k][j], vv = av[k][j];
            lsu += uu; lqu += uu*uu; lsv += vv; lqv += vv*vv;
        }
        atomicAdd(&s_su[co_l + j], lsu);
        atomicAdd(&s_qu[co_l + j], lqu);
        atomicAdd(&s_sv[co_l + j], lsv);
        atomicAdd(&s_qv[co_l + j], lqv);
        size_t o = (((size_t)b*CHAN + co0 + co_l + j)*HH + h)*WW + p0;
        *(float4*)&g_u[o] = make_float4(au[0][j], au[1][j], au[2][j], au[3][j]);
        *(float4*)&g_v[o] = make_float4(av[0][j], av[1][j], av[2][j], av[3][j]);
    }
    __syncthreads();
    if (tid < 64) {
        atomicAdd(&g_stats[2*CHAN + co0 + tid], s_su[tid]);
        atomicAdd(&g_stats[3*CHAN + co0 + tid], s_qu[tid]);
        atomicAdd(&g_stats[4*CHAN + co0 + tid], s_sv[tid]);
        atomicAdd(&g_stats[5*CHAN + co0 + tid], s_qv[tid]);
    }
}

// ---------------- final: out = silu(bn2(u) + bns(v)) ----------------
__global__ void k_final(float* __restrict__ out,
                        const float* __restrict__ g2, const float* __restrict__ be2,
                        const float* __restrict__ gs, const float* __restrict__ bes) {
    int i4 = blockIdx.x * blockDim.x + threadIdx.x;
    size_t base = (size_t)i4 * 4;
    if (base >= (size_t)BATCH*CHAN*HWSZ) return;
    int c = (int)((base >> 12) & 255);

    float mu = g_stats[2*CHAN + c] * (1.f / (float)NHW);
    float vu = g_stats[3*CHAN + c] * (1.f / (float)NHW) - mu*mu;
    float su = g2[c] * rsqrtf(vu + EPSBN);
    float bu = be2[c] - mu * su;

    float mv = g_stats[4*CHAN + c] * (1.f / (float)NHW);
    float vv = g_stats[5*CHAN + c] * (1.f / (float)NHW) - mv*mv;
    float sv = gs[c] * rsqrtf(vv + EPSBN);
    float bv = bes[c] - mv * sv;

    float4 u = *(const float4*)&g_u[base];
    float4 v = *(const float4*)&g_v[base];
    float4 o;
    {
        float z;
        z = fmaf(u.x, su, bu) + fmaf(v.x, sv, bv); o.x = siluf_(z);
        z = fmaf(u.y, su, bu) + fmaf(v.y, sv, bv); o.y = siluf_(z);
        z = fmaf(u.z, su, bu) + fmaf(v.z, sv, bv); o.z = siluf_(z);
        z = fmaf(u.w, su, bu) + fmaf(v.w, sv, bv); o.w = siluf_(z);
    }
    *(float4*)&out[base] = o;
}

// ---------------- launch ----------------
extern "C" void kernel_launch(void* const* d_in, const int* in_sizes, int n_in,
                              void* d_out, int out_size) {
    const float* x        = (const float*)d_in[0];
    const float* dce      = (const float*)d_in[1];
    const float* w_dce    = (const float*)d_in[2];
    const float* b_dce    = (const float*)d_in[3];
    const float* w_ch     = (const float*)d_in[4];
    const float* w_shrink = (const float*)d_in[5];
    const float* b_shrink = (const float*)d_in[6];
    const float* w_expand = (const float*)d_in[7];
    const float* b_expand = (const float*)d_in[8];
    const float* w_conv1  = (const float*)d_in[9];
    const float* g_bn1    = (const float*)d_in[10];
    const float* be_bn1   = (const float*)d_in[11];
    const float* w_conv2  = (const float*)d_in[12];
    const float* g_bn2    = (const float*)d_in[13];
    const float* be_bn2   = (const float*)d_in[14];
    const float* w_sc     = (const float*)d_in[15];
    const float* g_bns    = (const float*)d_in[16];
    const float* be_bns   = (const float*)d_in[17];
    float* out = (float*)d_out;

    k_zero_stats<<<6, 256>>>();
    k_spatial<<<BATCH*CHAN, 256>>>(x, w_ch);
    k_mod<<<BATCH, 128>>>(dce, w_dce, b_dce, w_shrink, b_shrink, w_expand, b_expand);
    k_transpose<<<256, 256>>>(w_conv2, w_sc);
    k_w1t<<<(9*CHAN*CHAN + 255)/256, 256>>>(w_conv1);
    k_conv1_mma<<<dim3(32, 4, BATCH), 256>>>(x);
    k_gemm<<<dim3(BATCH*HH, 4), 256>>>(x, g_bn1, be_bn1);
    k_final<<<(BATCH*CHAN*HWSZ/4 + 255)/256, 256>>>(out, g_bn2, be_bn2, g_bns, be_bns);
}

// round 3
// speedup vs baseline: 3.0909x; 1.9634x over previous
#include <cuda_runtime.h>
#include <math.h>
#include <stdint.h>

#define BATCH 16
#define CHAN  256
#define HH    64
#define WW    64
#define HWSZ  4096
#define NHW   65536   // BATCH*HH*WW
#define EPSBN 1e-5f

// ---------------- scratch (device globals; no allocation allowed) ----------------
__device__ float g_t1[BATCH*CHAN*HWSZ];                   // conv1 output (fp32)
__device__ float g_u [BATCH*CHAN*HWSZ];                   // conv2 output (pre-bn2)
__device__ float g_v [BATCH*CHAN*HWSZ];                   // shortcut output (pre-bns)
__device__ __align__(16) uint32_t g_a [BATCH*CHAN*HWSZ];  // silu(bn1(t1)) tf32
__device__ __align__(16) uint32_t g_xm[BATCH*CHAN*HWSZ];  // x*mod tf32
__device__ __align__(16) uint32_t g_w2t [CHAN*CHAN];      // w_conv2^T tf32 [ci][co]
__device__ __align__(16) uint32_t g_wsct[CHAN*CHAN];      // w_sc^T   tf32 [ci][co]
__device__ __align__(16) uint32_t g_w1t[9*CHAN*CHAN];     // w_conv1 tf32 [tap][ci][co]
__device__ float g_spatial[BATCH*CHAN];
__device__ float g_mod    [BATCH*CHAN];
// [0:C) sum_t1, [C:2C) sq_t1, [2C:3C) sum_u, [3C:4C) sq_u, [4C:5C) sum_v, [5C:6C) sq_v
__device__ float g_stats[6*CHAN];

__device__ __forceinline__ float sigmoidf_(float z) { return 1.f / (1.f + expf(-z)); }
__device__ __forceinline__ float siluf_(float z)    { return z / (1.f + expf(-z)); }

__device__ __forceinline__ uint32_t f2tf32(float f) {
    uint32_t u;
    asm("cvt.rna.tf32.f32 %0, %1;" : "=r"(u) : "f"(f));
    return u;
}

__device__ __forceinline__ void mma_tf32(float* c, uint32_t a0, uint32_t a1,
                                         uint32_t a2, uint32_t a3,
                                         uint32_t b0, uint32_t b1) {
    asm volatile(
        "mma.sync.aligned.m16n8k8.row.col.f32.tf32.tf32.f32 "
        "{%0,%1,%2,%3}, {%4,%5,%6,%7}, {%8,%9}, {%0,%1,%2,%3};"
        : "+f"(c[0]), "+f"(c[1]), "+f"(c[2]), "+f"(c[3])
        : "r"(a0), "r"(a1), "r"(a2), "r"(a3), "r"(b0), "r"(b1));
}

// ---------------- zero the stats accumulators ----------------
__global__ void k_zero_stats() {
    int i = blockIdx.x * blockDim.x + threadIdx.x;
    if (i < 6*CHAN) g_stats[i] = 0.f;
}

// ---------------- spatial proj: mean over HW of depthwise 3x3 conv(x) ----------------
__global__ void k_spatial(const float* __restrict__ x, const float* __restrict__ w_ch) {
    int bc = blockIdx.x;
    int c  = bc & (CHAN-1);
    const float* xp = x + (size_t)bc * HWSZ;
    float wk[9];
#pragma unroll
    for (int i = 0; i < 9; i++) wk[i] = w_ch[c*9 + i];

    float acc = 0.f;
    for (int i = threadIdx.x; i < HWSZ; i += blockDim.x) {
        int h = i >> 6, w = i & 63;
        float s = 0.f;
#pragma unroll
        for (int ky = 0; ky < 3; ky++) {
            int gh = h + ky - 1;
            if (gh < 0 || gh >= HH) continue;
#pragma unroll
            for (int kx = 0; kx < 3; kx++) {
                int gw = w + kx - 1;
                if (gw < 0 || gw >= WW) continue;
                s += wk[ky*3+kx] * xp[gh*WW + gw];
            }
        }
        acc += s;
    }
    __shared__ float red[256];
    red[threadIdx.x] = acc;
    __syncthreads();
    for (int s = 128; s > 0; s >>= 1) {
        if (threadIdx.x < s) red[threadIdx.x] += red[threadIdx.x + s];
        __syncthreads();
    }
    if (threadIdx.x == 0) g_spatial[bc] = red[0] * (1.f / (float)HWSZ);
}

// ---------------- gate MLP -> g_mod ----------------
__global__ void k_mod(const float* __restrict__ dce, const float* __restrict__ w_dce,
                      const float* __restrict__ b_dce, const float* __restrict__ w_sh,
                      const float* __restrict__ b_sh, const float* __restrict__ w_ex,
                      const float* __restrict__ b_ex) {
    int b = blockIdx.x;
    int t = threadIdx.x;                 // 128 threads
    __shared__ float pooled[128];
    __shared__ float mbuf[256];
    __shared__ float hbuf[128];

    {
        float s = 0.f;
        const float* dp = dce + (size_t)b * 100 * 128 + t;
        for (int l = 0; l < 100; l++) s += dp[l * 128];
        pooled[t] = s * 0.01f;
    }
    __syncthreads();

    for (int co = t; co < 256; co += 128) {
        float a = b_dce[co];
        const float* wr = w_dce + (size_t)co * 128;
        for (int j = 0; j < 128; j++) a += pooled[j] * wr[j];
        mbuf[co] = a * g_spatial[b*CHAN + co];
    }
    __syncthreads();

    {
        float a = b_sh[t];
        const float* wr = w_sh + (size_t)t * 256;
        for (int i = 0; i < 256; i++) a += mbuf[i] * wr[i];
        hbuf[t] = fmaxf(a, 0.f);
    }
    __syncthreads();

    for (int co = t; co < 256; co += 128) {
        float a = b_ex[co];
        const float* wr = w_ex + (size_t)co * 128;
        for (int i = 0; i < 128; i++) a += hbuf[i] * wr[i];
        g_mod[b*CHAN + co] = sigmoidf_(a);
    }
}

// ---------------- transpose 1x1 weights (to tf32) ----------------
__global__ void k_transpose(const float* __restrict__ w2, const float* __restrict__ wsc) {
    int idx = blockIdx.x * blockDim.x + threadIdx.x;
    if (idx >= CHAN*CHAN) return;
    int co = idx >> 8, ci = idx & 255;
    g_w2t [ci*CHAN + co] = f2tf32(w2 [idx]);
    g_wsct[ci*CHAN + co] = f2tf32(wsc[idx]);
}

// ---------------- conv1 weights to [tap][ci][co], tf32 ----------------
__global__ void k_w1t(const float* __restrict__ w1) {
    int idx = blockIdx.x * blockDim.x + threadIdx.x;
    if (idx >= 9*CHAN*CHAN) return;
    int tap = idx >> 16;
    int rem = idx & 65535;
    int ci  = rem >> 8;
    int co  = rem & 255;
    g_w1t[idx] = f2tf32(w1[(size_t)co*2304 + ci*9 + tap]);
}

// ---------------- conv1 via tf32 mma.sync: 9 shifted GEMMs, B hoisted ----------------
// grid: (32 tiles 16x8, 4 cout groups of 64, 16 batches), 256 threads (8 warps)
#define PSTR 185
#define BSTR 68
#define CONV_SMEM_WORDS (16*PSTR + 9*16*BSTR)
__global__ void __launch_bounds__(256) k_conv1_mma(const float* __restrict__ x) {
    extern __shared__ uint32_t smem_dyn[];
    uint32_t* s_in = smem_dyn;                 // 16 cin x 18x10 halo patch
    uint32_t* s_b  = smem_dyn + 16*PSTR;       // [tap][k16][co64] stride 68

    __shared__ float s_sum[64], s_sq[64];

    int b    = blockIdx.z;
    int co0  = blockIdx.y * 64;
    int tile = blockIdx.x;
    int th0  = (tile >> 3) * 16;
    int tw0  = (tile & 7) * 8;

    int tid  = threadIdx.x;
    int warp = tid >> 5;
    int lane = tid & 31;
    int gid  = lane >> 2;
    int tq   = lane & 3;
    int w2   = warp * 2;

    if (tid < 64) { s_sum[tid] = 0.f; s_sq[tid] = 0.f; }

    float acc[8][4];
#pragma unroll
    for (int j = 0; j < 8; j++)
#pragma unroll
        for (int k = 0; k < 4; k++) acc[j][k] = 0.f;

    const float* modp = g_mod + b*CHAN;

    for (int c0 = 0; c0 < CHAN; c0 += 16) {
        __syncthreads();   // protect smem from previous iteration's reads
        // input halo patch (mod applied, tf32)
        for (int idx = tid; idx < 16*180; idx += 256) {
            int ci = idx / 180, r = idx - ci*180;
            int iy = r / 10, ix = r - iy*10;
            int gh = th0 + iy - 1, gw = tw0 + ix - 1;
            float v = 0.f;
            if (gh >= 0 && gh < HH && gw >= 0 && gw < WW)
                v = x[(((size_t)b*CHAN + c0 + ci)*HH + gh)*WW + gw] * modp[c0 + ci];
            s_in[ci*PSTR + iy*10 + ix] = f2tf32(v);
        }
        // all 9 taps of B: 9216 words as 2304 uint4
        for (int idx4 = tid; idx4 < 2304; idx4 += 256) {
            int w   = idx4 * 4;
            int tap = w >> 10;
            int rem = w & 1023;
            int kk  = rem >> 6;
            int co  = rem & 63;
            uint4 val = *reinterpret_cast<const uint4*>(
                g_w1t + (size_t)tap*65536 + (size_t)(c0+kk)*256 + co0 + co);
            *reinterpret_cast<uint4*>(s_b + (tap*16 + kk)*BSTR + co) = val;
        }
        __syncthreads();

#pragma unroll
        for (int tap = 0; tap < 9; tap++) {
            int ky = tap / 3, kx = tap - ky*3;
            int arow = (w2 + ky)*10 + gid + kx;
#pragma unroll
            for (int kk0 = 0; kk0 < 16; kk0 += 8) {
                const uint32_t* ap = s_in + (kk0 + tq)*PSTR + arow;
                uint32_t a0 = ap[0];
                uint32_t a1 = ap[10];
                uint32_t a2 = ap[4*PSTR];
                uint32_t a3 = ap[4*PSTR + 10];
                const uint32_t* bp = s_b + (tap*16 + kk0 + tq)*BSTR + gid;
#pragma unroll
                for (int j = 0; j < 8; j++) {
                    uint32_t b0 = bp[j*8];
                    uint32_t b1 = bp[j*8 + 4*BSTR];
                    mma_tf32(acc[j], a0, a1, a2, a3, b0, b1);
                }
            }
        }
    }

    // store + bn1 partial stats
    int py0 = th0 + w2;
    int px  = tw0 + gid;
#pragma unroll
    for (int j = 0; j < 8; j++) {
        int co = co0 + j*8 + tq*2;
        size_t o0 = (((size_t)b*CHAN + co)*HH + py0)*WW + px;
        g_t1[o0]             = acc[j][0];
        g_t1[o0 + HWSZ]      = acc[j][1];
        g_t1[o0 + WW]        = acc[j][2];
        g_t1[o0 + HWSZ + WW] = acc[j][3];

        float s0 = acc[j][0] + acc[j][2];
        float s1 = acc[j][1] + acc[j][3];
        float q0 = acc[j][0]*acc[j][0] + acc[j][2]*acc[j][2];
        float q1 = acc[j][1]*acc[j][1] + acc[j][3]*acc[j][3];
#pragma unroll
        for (int o = 4; o < 32; o <<= 1) {
            s0 += __shfl_xor_sync(0xffffffffu, s0, o);
            s1 += __shfl_xor_sync(0xffffffffu, s1, o);
            q0 += __shfl_xor_sync(0xffffffffu, q0, o);
            q1 += __shfl_xor_sync(0xffffffffu, q1, o);
        }
        if (gid == 0) {
            atomicAdd(&s_sum[j*8 + tq*2],     s0);
            atomicAdd(&s_sum[j*8 + tq*2 + 1], s1);
            atomicAdd(&s_sq [j*8 + tq*2],     q0);
            atomicAdd(&s_sq [j*8 + tq*2 + 1], q1);
        }
    }
    __syncthreads();
    if (tid < 64) {
        atomicAdd(&g_stats[co0 + tid],        s_sum[tid]);
        atomicAdd(&g_stats[CHAN + co0 + tid], s_sq[tid]);
    }
}

// ---------------- prep: g_a = tf32(silu(bn1(t1))), g_xm = tf32(x*mod) ----------------
__global__ void k_prep(const float* __restrict__ x,
                       const float* __restrict__ g1, const float* __restrict__ be1) {
    int i4 = blockIdx.x * blockDim.x + threadIdx.x;
    size_t base = (size_t)i4 * 4;
    if (base >= (size_t)BATCH*CHAN*HWSZ) return;
    int c = (int)((base >> 12) & 255);
    int b = (int)(base >> 20);

    float mean = g_stats[c] * (1.f / (float)NHW);
    float var  = g_stats[CHAN + c] * (1.f / (float)NHW) - mean*mean;
    float sc   = g1[c] * rsqrtf(var + EPSBN);
    float sh   = be1[c] - mean * sc;
    float mv   = g_mod[b*CHAN + c];

    float4 t = *(const float4*)&g_t1[base];
    float4 xv = *(const float4*)&x[base];
    uint4 a, m;
    a.x = f2tf32(siluf_(fmaf(t.x, sc, sh)));
    a.y = f2tf32(siluf_(fmaf(t.y, sc, sh)));
    a.z = f2tf32(siluf_(fmaf(t.z, sc, sh)));
    a.w = f2tf32(siluf_(fmaf(t.w, sc, sh)));
    m.x = f2tf32(xv.x * mv);
    m.y = f2tf32(xv.y * mv);
    m.z = f2tf32(xv.z * mv);
    m.w = f2tf32(xv.w * mv);
    *reinterpret_cast<uint4*>(&g_a [base]) = a;
    *reinterpret_cast<uint4*>(&g_xm[base]) = m;
}

// ---------------- dual 1x1 GEMM via tf32 mma: u = w2 @ a, v = wsc @ xm ----------------
// grid: (B*H = 1024, 4 cout groups of 64), 256 threads (8 warps)
// warp: m-tile (w&3)*16 pixels, n-half (w>>2)*32 couts
#define GST 68
__global__ void __launch_bounds__(256) k_gemm_mma() {
    __shared__ uint32_t s_a [32*GST];
    __shared__ uint32_t s_m [32*GST];
    __shared__ uint32_t s_w2[32*GST];
    __shared__ uint32_t s_ws[32*GST];
    __shared__ float s_su[64], s_qu[64], s_sv[64], s_qv[64];

    int bh  = blockIdx.x;
    int b   = bh >> 6;
    int h   = bh & 63;
    int co0 = blockIdx.y * 64;
    int tid = threadIdx.x;
    int warp = tid >> 5;
    int lane = tid & 31;
    int gid  = lane >> 2;
    int tq   = lane & 3;
    int mt   = (warp & 3) * 16;    // pixel tile base
    int n0   = (warp >> 2) * 32;   // local cout base

    if (tid < 64) { s_su[tid]=0.f; s_qu[tid]=0.f; s_sv[tid]=0.f; s_qv[tid]=0.f; }

    float au[4][4], av[4][4];
#pragma unroll
    for (int j = 0; j < 4; j++)
#pragma unroll
        for (int k = 0; k < 4; k++) { au[j][k] = 0.f; av[j][k] = 0.f; }

    size_t rowbase = (((size_t)b*CHAN)*HH + h)*WW;   // + cin*HWSZ + p

    for (int c0 = 0; c0 < CHAN; c0 += 32) {
        __syncthreads();
        for (int idx4 = tid; idx4 < 512; idx4 += 256) {
            int w  = idx4 * 4;
            int ci = w >> 6, p = w & 63;
            int cin = c0 + ci;
            size_t gi = rowbase + (size_t)cin*HWSZ + p;
            *reinterpret_cast<uint4*>(s_a + ci*GST + p) =
                *reinterpret_cast<const uint4*>(g_a + gi);
            *reinterpret_cast<uint4*>(s_m + ci*GST + p) =
                *reinterpret_cast<const uint4*>(g_xm + gi);
            *reinterpret_cast<uint4*>(s_w2 + ci*GST + p) =
                *reinterpret_cast<const uint4*>(g_w2t + (size_t)cin*CHAN + co0 + p);
            *reinterpret_cast<uint4*>(s_ws + ci*GST + p) =
                *reinterpret_cast<const uint4*>(g_wsct + (size_t)cin*CHAN + co0 + p);
        }
        __syncthreads();

#pragma unroll
        for (int k0 = 0; k0 < 32; k0 += 8) {
            const uint32_t* apa = s_a + (k0 + tq)*GST + mt + gid;
            uint32_t ua0 = apa[0];
            uint32_t ua1 = apa[8];
            uint32_t ua2 = apa[4*GST];
            uint32_t ua3 = apa[4*GST + 8];
            const uint32_t* apm = s_m + (k0 + tq)*GST + mt + gid;
            uint32_t va0 = apm[0];
            uint32_t va1 = apm[8];
            uint32_t va2 = apm[4*GST];
            uint32_t va3 = apm[4*GST + 8];
            const uint32_t* bpu = s_w2 + (k0 + tq)*GST + n0 + gid;
            const uint32_t* bpv = s_ws + (k0 + tq)*GST + n0 + gid;
#pragma unroll
            for (int j = 0; j < 4; j++) {
                uint32_t b0 = bpu[j*8];
                uint32_t b1 = bpu[j*8 + 4*GST];
                mma_tf32(au[j], ua0, ua1, ua2, ua3, b0, b1);
                uint32_t c0r = bpv[j*8];
                uint32_t c1r = bpv[j*8 + 4*GST];
                mma_tf32(av[j], va0, va1, va2, va3, c0r, c1r);
            }
        }
    }

    // store + stats
    int p = mt + gid;
#pragma unroll
    for (int j = 0; j < 4; j++) {
        int co = co0 + n0 + j*8 + tq*2;
        size_t o0 = (((size_t)b*CHAN + co)*HH + h)*WW + p;
        g_u[o0]            = au[j][0];
        g_u[o0 + HWSZ]     = au[j][1];
        g_u[o0 + 8]        = au[j][2];
        g_u[o0 + HWSZ + 8] = au[j][3];
        g_v[o0]            = av[j][0];
        g_v[o0 + HWSZ]     = av[j][1];
        g_v[o0 + 8]        = av[j][2];
        g_v[o0 + HWSZ + 8] = av[j][3];

        float su0 = au[j][0] + au[j][2], su1 = au[j][1] + au[j][3];
        float qu0 = au[j][0]*au[j][0] + au[j][2]*au[j][2];
        float qu1 = au[j][1]*au[j][1] + au[j][3]*au[j][3];
        float sv0 = av[j][0] + av[j][2], sv1 = av[j][1] + av[j][3];
        float qv0 = av[j][0]*av[j][0] + av[j][2]*av[j][2];
        float qv1 = av[j][1]*av[j][1] + av[j][3]*av[j][3];
#pragma unroll
        for (int o = 4; o < 32; o <<= 1) {
            su0 += __shfl_xor_sync(0xffffffffu, su0, o);
            su1 += __shfl_xor_sync(0xffffffffu, su1, o);
            qu0 += __shfl_xor_sync(0xffffffffu, qu0, o);
            qu1 += __shfl_xor_sync(0xffffffffu, qu1, o);
            sv0 += __shfl_xor_sync(0xffffffffu, sv0, o);
            sv1 += __shfl_xor_sync(0xffffffffu, sv1, o);
            qv0 += __shfl_xor_sync(0xffffffffu, qv0, o);
            qv1 += __shfl_xor_sync(0xffffffffu, qv1, o);
        }
        if (gid == 0) {
            int nn = n0 + j*8 + tq*2;
            atomicAdd(&s_su[nn],   su0); atomicAdd(&s_su[nn+1], su1);
            atomicAdd(&s_qu[nn],   qu0); atomicAdd(&s_qu[nn+1], qu1);
            atomicAdd(&s_sv[nn],   sv0); atomicAdd(&s_sv[nn+1], sv1);
            atomicAdd(&s_qv[nn],   qv0); atomicAdd(&s_qv[nn+1], qv1);
        }
    }
    __syncthreads();
    if (tid < 64) {
        atomicAdd(&g_stats[2*CHAN + co0 + tid], s_su[tid]);
        atomicAdd(&g_stats[3*CHAN + co0 + tid], s_qu[tid]);
        atomicAdd(&g_stats[4*CHAN + co0 + tid], s_sv[tid]);
        atomicAdd(&g_stats[5*CHAN + co0 + tid], s_qv[tid]);
    }
}

// ---------------- final: out = silu(bn2(u) + bns(v)) ----------------
__global__ void k_final(float* __restrict__ out,
                        const float* __restrict__ g2, const float* __restrict__ be2,
                        const float* __restrict__ gs, const float* __restrict__ bes) {
    int i4 = blockIdx.x * blockDim.x + threadIdx.x;
    size_t base = (size_t)i4 * 4;
    if (base >= (size_t)BATCH*CHAN*HWSZ) return;
    int c = (int)((base >> 12) & 255);

    float mu = g_stats[2*CHAN + c] * (1.f / (float)NHW);
    float vu = g_stats[3*CHAN + c] * (1.f / (float)NHW) - mu*mu;
    float su = g2[c] * rsqrtf(vu + EPSBN);
    float bu = be2[c] - mu * su;

    float mv = g_stats[4*CHAN + c] * (1.f / (float)NHW);
    float vv = g_stats[5*CHAN + c] * (1.f / (float)NHW) - mv*mv;
    float sv = gs[c] * rsqrtf(vv + EPSBN);
    float bv = bes[c] - mv * sv;

    float4 u = *(const float4*)&g_u[base];
    float4 v = *(const float4*)&g_v[base];
    float4 o;
    {
        float z;
        z = fmaf(u.x, su, bu) + fmaf(v.x, sv, bv); o.x = siluf_(z);
        z = fmaf(u.y, su, bu) + fmaf(v.y, sv, bv); o.y = siluf_(z);
        z = fmaf(u.z, su, bu) + fmaf(v.z, sv, bv); o.z = siluf_(z);
        z = fmaf(u.w, su, bu) + fmaf(v.w, sv, bv); o.w = siluf_(z);
    }
    *(float4*)&out[base] = o;
}

// ---------------- launch ----------------
extern "C" void kernel_launch(void* const* d_in, const int* in_sizes, int n_in,
                              void* d_out, int out_size) {
    const float* x        = (const float*)d_in[0];
    const float* dce      = (const float*)d_in[1];
    const float* w_dce    = (const float*)d_in[2];
    const float* b_dce    = (const float*)d_in[3];
    const float* w_ch     = (const float*)d_in[4];
    const float* w_shrink = (const float*)d_in[5];
    const float* b_shrink = (const float*)d_in[6];
    const float* w_expand = (const float*)d_in[7];
    const float* b_expand = (const float*)d_in[8];
    const float* w_conv1  = (const float*)d_in[9];
    const float* g_bn1    = (const float*)d_in[10];
    const float* be_bn1   = (const float*)d_in[11];
    const float* w_conv2  = (const float*)d_in[12];
    const float* g_bn2    = (const float*)d_in[13];
    const float* be_bn2   = (const float*)d_in[14];
    const float* w_sc     = (const float*)d_in[15];
    const float* g_bns    = (const float*)d_in[16];
    const float* be_bns   = (const float*)d_in[17];
    float* out = (float*)d_out;

    const int conv_smem = CONV_SMEM_WORDS * 4;   // 51008 bytes
    cudaFuncSetAttribute(k_conv1_mma, cudaFuncAttributeMaxDynamicSharedMemorySize, conv_smem);

    k_zero_stats<<<6, 256>>>();
    k_spatial<<<BATCH*CHAN, 256>>>(x, w_ch);
    k_mod<<<BATCH, 128>>>(dce, w_dce, b_dce, w_shrink, b_shrink, w_expand, b_expand);
    k_transpose<<<256, 256>>>(w_conv2, w_sc);
    k_w1t<<<(9*CHAN*CHAN + 255)/256, 256>>>(w_conv1);
    k_conv1_mma<<<dim3(32, 4, BATCH), 256, conv_smem>>>(x);
    k_prep<<<(BATCH*CHAN*HWSZ/4 + 255)/256, 256>>>(x, g_bn1, be_bn1);
    k_gemm_mma<<<dim3(BATCH*HH, 4), 256>>>();
    k_final<<<(BATCH*CHAN*HWSZ/4 + 255)/256, 256>>>(out, g_bn2, be_bn2, g_bns, be_bns);
}

// round 4
// speedup vs baseline: 3.5147x; 1.1371x over previous
#include <cuda_runtime.h>
#include <math.h>
#include <stdint.h>

#define BATCH 16
#define CHAN  256
#define HH    64
#define WW    64
#define HWSZ  4096
#define NHW   65536   // BATCH*HH*WW
#define EPSBN 1e-5f

// ---------------- scratch (device globals; no allocation allowed) ----------------
__device__ float g_t1[BATCH*CHAN*HWSZ];                   // conv1 output (fp32)
__device__ float g_u [BATCH*CHAN*HWSZ];                   // conv2 output (pre-bn2)
__device__ float g_v [BATCH*CHAN*HWSZ];                   // shortcut output (pre-bns)
__device__ __align__(16) uint32_t g_a [BATCH*CHAN*HWSZ];  // silu(bn1(t1)) tf32
__device__ __align__(16) uint32_t g_xm[BATCH*CHAN*HWSZ];  // x*mod tf32
__device__ __align__(16) uint32_t g_w2t [CHAN*CHAN];      // w_conv2^T tf32 [ci][co]
__device__ __align__(16) uint32_t g_wsct[CHAN*CHAN];      // w_sc^T   tf32 [ci][co]
__device__ __align__(16) uint32_t g_w1t[9*CHAN*CHAN];     // w_conv1 tf32 [tap][ci][co]
__device__ float g_spatial[BATCH*CHAN];
__device__ float g_mod    [BATCH*CHAN];
// [0:C) sum_t1, [C:2C) sq_t1, [2C:3C) sum_u, [3C:4C) sq_u, [4C:5C) sum_v, [5C:6C) sq_v
__device__ float g_stats[6*CHAN];

__device__ __forceinline__ float sigmoidf_(float z) { return 1.f / (1.f + expf(-z)); }
__device__ __forceinline__ float siluf_(float z)    { return z / (1.f + expf(-z)); }

__device__ __forceinline__ uint32_t f2tf32(float f) {
    uint32_t u;
    asm("cvt.rna.tf32.f32 %0, %1;" : "=r"(u) : "f"(f));
    return u;
}

__device__ __forceinline__ void mma_tf32(float* c, uint32_t a0, uint32_t a1,
                                         uint32_t a2, uint32_t a3,
                                         uint32_t b0, uint32_t b1) {
    asm volatile(
        "mma.sync.aligned.m16n8k8.row.col.f32.tf32.tf32.f32 "
        "{%0,%1,%2,%3}, {%4,%5,%6,%7}, {%8,%9}, {%0,%1,%2,%3};"
        : "+f"(c[0]), "+f"(c[1]), "+f"(c[2]), "+f"(c[3])
        : "r"(a0), "r"(a1), "r"(a2), "r"(a3), "r"(b0), "r"(b1));
}

// ---------------- zero the stats accumulators ----------------
__global__ void k_zero_stats() {
    int i = blockIdx.x * blockDim.x + threadIdx.x;
    if (i < 6*CHAN) g_stats[i] = 0.f;
}

// ---------------- spatial proj: mean over HW of depthwise 3x3 conv(x) ----------------
__global__ void k_spatial(const float* __restrict__ x, const float* __restrict__ w_ch) {
    int bc = blockIdx.x;
    int c  = bc & (CHAN-1);
    const float* xp = x + (size_t)bc * HWSZ;
    float wk[9];
#pragma unroll
    for (int i = 0; i < 9; i++) wk[i] = w_ch[c*9 + i];

    float acc = 0.f;
    for (int i = threadIdx.x; i < HWSZ; i += blockDim.x) {
        int h = i >> 6, w = i & 63;
        float s = 0.f;
#pragma unroll
        for (int ky = 0; ky < 3; ky++) {
            int gh = h + ky - 1;
            if (gh < 0 || gh >= HH) continue;
#pragma unroll
            for (int kx = 0; kx < 3; kx++) {
                int gw = w + kx - 1;
                if (gw < 0 || gw >= WW) continue;
                s += wk[ky*3+kx] * xp[gh*WW + gw];
            }
        }
        acc += s;
    }
    __shared__ float red[256];
    red[threadIdx.x] = acc;
    __syncthreads();
    for (int s = 128; s > 0; s >>= 1) {
        if (threadIdx.x < s) red[threadIdx.x] += red[threadIdx.x + s];
        __syncthreads();
    }
    if (threadIdx.x == 0) g_spatial[bc] = red[0] * (1.f / (float)HWSZ);
}

// ---------------- gate MLP -> g_mod ----------------
__global__ void k_mod(const float* __restrict__ dce, const float* __restrict__ w_dce,
                      const float* __restrict__ b_dce, const float* __restrict__ w_sh,
                      const float* __restrict__ b_sh, const float* __restrict__ w_ex,
                      const float* __restrict__ b_ex) {
    int b = blockIdx.x;
    int t = threadIdx.x;                 // 128 threads
    __shared__ float pooled[128];
    __shared__ float mbuf[256];
    __shared__ float hbuf[128];

    {
        float s = 0.f;
        const float* dp = dce + (size_t)b * 100 * 128 + t;
        for (int l = 0; l < 100; l++) s += dp[l * 128];
        pooled[t] = s * 0.01f;
    }
    __syncthreads();

    for (int co = t; co < 256; co += 128) {
        float a = b_dce[co];
        const float* wr = w_dce + (size_t)co * 128;
        for (int j = 0; j < 128; j++) a += pooled[j] * wr[j];
        mbuf[co] = a * g_spatial[b*CHAN + co];
    }
    __syncthreads();

    {
        float a = b_sh[t];
        const float* wr = w_sh + (size_t)t * 256;
        for (int i = 0; i < 256; i++) a += mbuf[i] * wr[i];
        hbuf[t] = fmaxf(a, 0.f);
    }
    __syncthreads();

    for (int co = t; co < 256; co += 128) {
        float a = b_ex[co];
        const float* wr = w_ex + (size_t)co * 128;
        for (int i = 0; i < 128; i++) a += hbuf[i] * wr[i];
        g_mod[b*CHAN + co] = sigmoidf_(a);
    }
}

// ---------------- transpose 1x1 weights (to tf32) ----------------
__global__ void k_transpose(const float* __restrict__ w2, const float* __restrict__ wsc) {
    int idx = blockIdx.x * blockDim.x + threadIdx.x;
    if (idx >= CHAN*CHAN) return;
    int co = idx >> 8, ci = idx & 255;
    g_w2t [ci*CHAN + co] = f2tf32(w2 [idx]);
    g_wsct[ci*CHAN + co] = f2tf32(wsc[idx]);
}

// ---------------- conv1 weights to [tap][ci][co], tf32 ----------------
__global__ void k_w1t(const float* __restrict__ w1) {
    int idx = blockIdx.x * blockDim.x + threadIdx.x;
    if (idx >= 9*CHAN*CHAN) return;
    int tap = idx >> 16;
    int rem = idx & 65535;
    int ci  = rem >> 8;
    int co  = rem & 255;
    g_w1t[idx] = f2tf32(w1[(size_t)co*2304 + ci*9 + tap]);
}

// ---------------- conv1 via tf32 mma.sync: 9 shifted GEMMs ----------------
// Block tile: M=128 pixels (16 rows x 8 cols), N=128 couts.
// Warps 4(M) x 2(N): each warp M=32 pixels (4 rows), N=64 couts.
// Pair-packed smem (k, k+4 as uint2) -> every fragment load is one LDS.64.
// grid: (32 tiles, 2 cout halves, 16 batches), 256 threads.
#define PPITCH 180                         // uint2 per pair-channel patch (18*10), %16==4 -> 2*180%32==8
#define BPITCH 132                         // uint2 per B row, 2*132%32==8
#define CONV_SMEM_BYTES ((8*PPITCH + 72*BPITCH) * 8)   // 87552
__global__ void __launch_bounds__(256) k_conv1_mma(const float* __restrict__ x) {
    extern __shared__ uint2 sm2[];
    uint2* p2 = sm2;                 // [pair 0..7][18*10]
    uint2* b2 = sm2 + 8*PPITCH;      // [tap*8 + kh*4 + tq][128 co + pad]

    __shared__ float s_sum[128], s_sq[128];

    int b    = blockIdx.z;
    int co0  = blockIdx.y * 128;
    int tile = blockIdx.x;
    int th0  = (tile >> 3) * 16;
    int tw0  = (tile & 7) * 8;

    int tid  = threadIdx.x;
    int warp = tid >> 5;
    int lane = tid & 31;
    int gid  = lane >> 2;
    int tq   = lane & 3;
    int wm   = warp & 3;      // warp row: pixel rows [wm*4, wm*4+4)
    int wn   = warp >> 2;     // cout half: local co [wn*64, wn*64+64)

    if (tid < 128) { s_sum[tid] = 0.f; s_sq[tid] = 0.f; }

    float acc[2][8][4];
#pragma unroll
    for (int t = 0; t < 2; t++)
#pragma unroll
        for (int j = 0; j < 8; j++)
#pragma unroll
            for (int k = 0; k < 4; k++) acc[t][j][k] = 0.f;

    const float* modp = g_mod + b*CHAN;

    for (int c0 = 0; c0 < CHAN; c0 += 16) {
        __syncthreads();   // protect smem from previous iteration's reads

        // ---- input halo patch, pair-packed: pair pr=(kh*4+tq) holds (ci, ci+4) ----
        for (int idx = tid; idx < 8*180; idx += 256) {
            int pr = idx / 180, r = idx - pr*180;
            int iy = r / 10, ix = r - iy*10;
            int kh = pr >> 2, tql = pr & 3;
            int ci = c0 + kh*8 + tql;
            int gh = th0 + iy - 1, gw = tw0 + ix - 1;
            float va = 0.f, vb = 0.f;
            if (gh >= 0 && gh < HH && gw >= 0 && gw < WW) {
                size_t gbase = (((size_t)b*CHAN + ci)*HH + gh)*WW + gw;
                va = x[gbase]            * modp[ci];
                vb = x[gbase + 4*HWSZ]   * modp[ci + 4];
            }
            p2[pr*PPITCH + r] = make_uint2(f2tf32(va), f2tf32(vb));
        }

        // ---- all 9 taps of B, pair-packed ----
        for (int idx = tid; idx < 2304; idx += 256) {
            int tap = idx >> 8;              // 0..8
            int rem = idx & 255;             // p(0..7) * co4(0..31)
            int p   = rem >> 5, co4 = rem & 31;
            int kh  = p >> 2, tql = p & 3;
            int ci  = c0 + kh*8 + tql;
            const uint32_t* gsrc = g_w1t + (size_t)tap*65536 + (size_t)ci*256 + co0 + co4*4;
            uint4 wa = *reinterpret_cast<const uint4*>(gsrc);
            uint4 wb = *reinterpret_cast<const uint4*>(gsrc + 4*256);
            uint2* dst = b2 + (tap*8 + p)*BPITCH + co4*4;
            *reinterpret_cast<uint4*>(dst)     = make_uint4(wa.x, wb.x, wa.y, wb.y);
            *reinterpret_cast<uint4*>(dst + 2) = make_uint4(wa.z, wb.z, wa.w, wb.w);
        }
        __syncthreads();

        // ---- mainloop: 9 taps x 2 k-halves, 16 MMAs each ----
        for (int tap = 0; tap < 9; tap++) {
            int ky = tap / 3, kx = tap - ky*3;
            int abase = ky*10 + gid + kx;
#pragma unroll
            for (int kh = 0; kh < 2; kh++) {
                uint2 aL[2], aH[2];
#pragma unroll
                for (int t = 0; t < 2; t++) {
                    int row0 = wm*4 + t*2;
                    const uint2* ap = p2 + (kh*4 + tq)*PPITCH + row0*10 + abase;
                    aL[t] = ap[0];     // (k=tq, k=tq+4) for pixel row row0
                    aH[t] = ap[10];    // same for row0+1 (m+8)
                }
                const uint2* bp = b2 + (tap*8 + kh*4 + tq)*BPITCH + wn*64 + gid;
#pragma unroll
                for (int j = 0; j < 8; j++) {
                    uint2 bb = bp[j*8];
#pragma unroll
                    for (int t = 0; t < 2; t++)
                        mma_tf32(acc[t][j], aL[t].x, aH[t].x, aL[t].y, aH[t].y, bb.x, bb.y);
                }
            }
        }
    }

    // ---- store + bn1 partial stats ----
    int px = tw0 + gid;
#pragma unroll
    for (int t = 0; t < 2; t++) {
        int gr = th0 + wm*4 + t*2;
#pragma unroll
        for (int j = 0; j < 8; j++) {
            int col = wn*64 + j*8 + tq*2;
            int co  = co0 + col;
            size_t o0 = (((size_t)b*CHAN + co)*HH + gr)*WW + px;
            float c0v = acc[t][j][0], c1v = acc[t][j][1];
            float c2v = acc[t][j][2], c3v = acc[t][j][3];
            g_t1[o0]             = c0v;
            g_t1[o0 + HWSZ]      = c1v;   // co+1
            g_t1[o0 + WW]        = c2v;   // row+1
            g_t1[o0 + HWSZ + WW] = c3v;

            float s0 = c0v + c2v;
            float s1 = c1v + c3v;
            float q0 = c0v*c0v + c2v*c2v;
            float q1 = c1v*c1v + c3v*c3v;
#pragma unroll
            for (int o = 4; o < 32; o <<= 1) {
                s0 += __shfl_xor_sync(0xffffffffu, s0, o);
                s1 += __shfl_xor_sync(0xffffffffu, s1, o);
                q0 += __shfl_xor_sync(0xffffffffu, q0, o);
                q1 += __shfl_xor_sync(0xffffffffu, q1, o);
            }
            if (gid == 0) {
                atomicAdd(&s_sum[col],     s0);
                atomicAdd(&s_sum[col + 1], s1);
                atomicAdd(&s_sq [col],     q0);
                atomicAdd(&s_sq [col + 1], q1);
            }
        }
    }
    __syncthreads();
    if (tid < 128) {
        atomicAdd(&g_stats[co0 + tid],        s_sum[tid]);
        atomicAdd(&g_stats[CHAN + co0 + tid], s_sq[tid]);
    }
}

// ---------------- prep: g_a = tf32(silu(bn1(t1))), g_xm = tf32(x*mod) ----------------
__global__ void k_prep(const float* __restrict__ x,
                       const float* __restrict__ g1, const float* __restrict__ be1) {
    int i4 = blockIdx.x * blockDim.x + threadIdx.x;
    size_t base = (size_t)i4 * 4;
    if (base >= (size_t)BATCH*CHAN*HWSZ) return;
    int c = (int)((base >> 12) & 255);
    int b = (int)(base >> 20);

    float mean = g_stats[c] * (1.f / (float)NHW);
    float var  = g_stats[CHAN + c] * (1.f / (float)NHW) - mean*mean;
    float sc   = g1[c] * rsqrtf(var + EPSBN);
    float sh   = be1[c] - mean * sc;
    float mv   = g_mod[b*CHAN + c];

    float4 t = *(const float4*)&g_t1[base];
    float4 xv = *(const float4*)&x[base];
    uint4 a, m;
    a.x = f2tf32(siluf_(fmaf(t.x, sc, sh)));
    a.y = f2tf32(siluf_(fmaf(t.y, sc, sh)));
    a.z = f2tf32(siluf_(fmaf(t.z, sc, sh)));
    a.w = f2tf32(siluf_(fmaf(t.w, sc, sh)));
    m.x = f2tf32(xv.x * mv);
    m.y = f2tf32(xv.y * mv);
    m.z = f2tf32(xv.z * mv);
    m.w = f2tf32(xv.w * mv);
    *reinterpret_cast<uint4*>(&g_a [base]) = a;
    *reinterpret_cast<uint4*>(&g_xm[base]) = m;
}

// ---------------- dual 1x1 GEMM via tf32 mma: u = w2 @ a, v = wsc @ xm ----------------
#define GST 68
__global__ void __launch_bounds__(256) k_gemm_mma() {
    __shared__ uint32_t s_a [32*GST];
    __shared__ uint32_t s_m [32*GST];
    __shared__ uint32_t s_w2[32*GST];
    __shared__ uint32_t s_ws[32*GST];
    __shared__ float s_su[64], s_qu[64], s_sv[64], s_qv[64];

    int bh  = blockIdx.x;
    int b   = bh >> 6;
    int h   = bh & 63;
    int co0 = blockIdx.y * 64;
    int tid = threadIdx.x;
    int warp = tid >> 5;
    int lane = tid & 31;
    int gid  = lane >> 2;
    int tq   = lane & 3;
    int mt   = (warp & 3) * 16;
    int n0   = (warp >> 2) * 32;

    if (tid < 64) { s_su[tid]=0.f; s_qu[tid]=0.f; s_sv[tid]=0.f; s_qv[tid]=0.f; }

    float au[4][4], av[4][4];
#pragma unroll
    for (int j = 0; j < 4; j++)
#pragma unroll
        for (int k = 0; k < 4; k++) { au[j][k] = 0.f; av[j][k] = 0.f; }

    size_t rowbase = (((size_t)b*CHAN)*HH + h)*WW;

    for (int c0 = 0; c0 < CHAN; c0 += 32) {
        __syncthreads();
        for (int idx4 = tid; idx4 < 512; idx4 += 256) {
            int w  = idx4 * 4;
            int ci = w >> 6, p = w & 63;
            int cin = c0 + ci;
            size_t gi = rowbase + (size_t)cin*HWSZ + p;
            *reinterpret_cast<uint4*>(s_a + ci*GST + p) =
                *reinterpret_cast<const uint4*>(g_a + gi);
            *reinterpret_cast<uint4*>(s_m + ci*GST + p) =
                *reinterpret_cast<const uint4*>(g_xm + gi);
            *reinterpret_cast<uint4*>(s_w2 + ci*GST + p) =
                *reinterpret_cast<const uint4*>(g_w2t + (size_t)cin*CHAN + co0 + p);
            *reinterpret_cast<uint4*>(s_ws + ci*GST + p) =
                *reinterpret_cast<const uint4*>(g_wsct + (size_t)cin*CHAN + co0 + p);
        }
        __syncthreads();

#pragma unroll
        for (int k0 = 0; k0 < 32; k0 += 8) {
            const uint32_t* apa = s_a + (k0 + tq)*GST + mt + gid;
            uint32_t ua0 = apa[0];
            uint32_t ua1 = apa[8];
            uint32_t ua2 = apa[4*GST];
            uint32_t ua3 = apa[4*GST + 8];
            const uint32_t* apm = s_m + (k0 + tq)*GST + mt + gid;
            uint32_t va0 = apm[0];
            uint32_t va1 = apm[8];
            uint32_t va2 = apm[4*GST];
            uint32_t va3 = apm[4*GST + 8];
            const uint32_t* bpu = s_w2 + (k0 + tq)*GST + n0 + gid;
            const uint32_t* bpv = s_ws + (k0 + tq)*GST + n0 + gid;
#pragma unroll
            for (int j = 0; j < 4; j++) {
                uint32_t b0 = bpu[j*8];
                uint32_t b1 = bpu[j*8 + 4*GST];
                mma_tf32(au[j], ua0, ua1, ua2, ua3, b0, b1);
                uint32_t c0r = bpv[j*8];
                uint32_t c1r = bpv[j*8 + 4*GST];
                mma_tf32(av[j], va0, va1, va2, va3, c0r, c1r);
            }
        }
    }

    int p = mt + gid;
#pragma unroll
    for (int j = 0; j < 4; j++) {
        int co = co0 + n0 + j*8 + tq*2;
        size_t o0 = (((size_t)b*CHAN + co)*HH + h)*WW + p;
        g_u[o0]            = au[j][0];
        g_u[o0 + HWSZ]     = au[j][1];
        g_u[o0 + 8]        = au[j][2];
        g_u[o0 + HWSZ + 8] = au[j][3];
        g_v[o0]            = av[j][0];
        g_v[o0 + HWSZ]     = av[j][1];
        g_v[o0 + 8]        = av[j][2];
        g_v[o0 + HWSZ + 8] = av[j][3];

        float su0 = au[j][0] + au[j][2], su1 = au[j][1] + au[j][3];
        float qu0 = au[j][0]*au[j][0] + au[j][2]*au[j][2];
        float qu1 = au[j][1]*au[j][1] + au[j][3]*au[j][3];
        float sv0 = av[j][0] + av[j][2], sv1 = av[j][1] + av[j][3];
        float qv0 = av[j][0]*av[j][0] + av[j][2]*av[j][2];
        float qv1 = av[j][1]*av[j][1] + av[j][3]*av[j][3];
#pragma unroll
        for (int o = 4; o < 32; o <<= 1) {
            su0 += __shfl_xor_sync(0xffffffffu, su0, o);
            su1 += __shfl_xor_sync(0xffffffffu, su1, o);
            qu0 += __shfl_xor_sync(0xffffffffu, qu0, o);
            qu1 += __shfl_xor_sync(0xffffffffu, qu1, o);
            sv0 += __shfl_xor_sync(0xffffffffu, sv0, o);
            sv1 += __shfl_xor_sync(0xffffffffu, sv1, o);
            qv0 += __shfl_xor_sync(0xffffffffu, qv0, o);
            qv1 += __shfl_xor_sync(0xffffffffu, qv1, o);
        }
        if (gid == 0) {
            int nn = n0 + j*8 + tq*2;
            atomicAdd(&s_su[nn],   su0); atomicAdd(&s_su[nn+1], su1);
            atomicAdd(&s_qu[nn],   qu0); atomicAdd(&s_qu[nn+1], qu1);
            atomicAdd(&s_sv[nn],   sv0); atomicAdd(&s_sv[nn+1], sv1);
            atomicAdd(&s_qv[nn],   qv0); atomicAdd(&s_qv[nn+1], qv1);
        }
    }
    __syncthreads();
    if (tid < 64) {
        atomicAdd(&g_stats[2*CHAN + co0 + tid], s_su[tid]);
        atomicAdd(&g_stats[3*CHAN + co0 + tid], s_qu[tid]);
        atomicAdd(&g_stats[4*CHAN + co0 + tid], s_sv[tid]);
        atomicAdd(&g_stats[5*CHAN + co0 + tid], s_qv[tid]);
    }
}

// ---------------- final: out = silu(bn2(u) + bns(v)) ----------------
__global__ void k_final(float* __restrict__ out,
                        const float* __restrict__ g2, const float* __restrict__ be2,
                        const float* __restrict__ gs, const float* __restrict__ bes) {
    int i4 = blockIdx.x * blockDim.x + threadIdx.x;
    size_t base = (size_t)i4 * 4;
    if (base >= (size_t)BATCH*CHAN*HWSZ) return;
    int c = (int)((base >> 12) & 255);

    float mu = g_stats[2*CHAN + c] * (1.f / (float)NHW);
    float vu = g_stats[3*CHAN + c] * (1.f / (float)NHW) - mu*mu;
    float su = g2[c] * rsqrtf(vu + EPSBN);
    float bu = be2[c] - mu * su;

    float mv = g_stats[4*CHAN + c] * (1.f / (float)NHW);
    float vv = g_stats[5*CHAN + c] * (1.f / (float)NHW) - mv*mv;
    float sv = gs[c] * rsqrtf(vv + EPSBN);
    float bv = bes[c] - mv * sv;

    float4 u = *(const float4*)&g_u[base];
    float4 v = *(const float4*)&g_v[base];
    float4 o;
    {
        float z;
        z = fmaf(u.x, su, bu) + fmaf(v.x, sv, bv); o.x = siluf_(z);
        z = fmaf(u.y, su, bu) + fmaf(v.y, sv, bv); o.y = siluf_(z);
        z = fmaf(u.z, su, bu) + fmaf(v.z, sv, bv); o.z = siluf_(z);
        z = fmaf(u.w, su, bu) + fmaf(v.w, sv, bv); o.w = siluf_(z);
    }
    *(float4*)&out[base] = o;
}

// ---------------- launch ----------------
extern "C" void kernel_launch(void* const* d_in, const int* in_sizes, int n_in,
                              void* d_out, int out_size) {
    const float* x        = (const float*)d_in[0];
    const float* dce      = (const float*)d_in[1];
    const float* w_dce    = (const float*)d_in[2];
    const float* b_dce    = (const float*)d_in[3];
    const float* w_ch     = (const float*)d_in[4];
    const float* w_shrink = (const float*)d_in[5];
    const float* b_shrink = (const float*)d_in[6];
    const float* w_expand = (const float*)d_in[7];
    const float* b_expand = (const float*)d_in[8];
    const float* w_conv1  = (const float*)d_in[9];
    const float* g_bn1    = (const float*)d_in[10];
    const float* be_bn1   = (const float*)d_in[11];
    const float* w_conv2  = (const float*)d_in[12];
    const float* g_bn2    = (const float*)d_in[13];
    const float* be_bn2   = (const float*)d_in[14];
    const float* w_sc     = (const float*)d_in[15];
    const float* g_bns    = (const float*)d_in[16];
    const float* be_bns   = (const float*)d_in[17];
    float* out = (float*)d_out;

    cudaFuncSetAttribute(k_conv1_mma, cudaFuncAttributeMaxDynamicSharedMemorySize,
                         CONV_SMEM_BYTES);

    k_zero_stats<<<6, 256>>>();
    k_spatial<<<BATCH*CHAN, 256>>>(x, w_ch);
    k_mod<<<BATCH, 128>>>(dce, w_dce, b_dce, w_shrink, b_shrink, w_expand, b_expand);
    k_transpose<<<256, 256>>>(w_conv2, w_sc);
    k_w1t<<<(9*CHAN*CHAN + 255)/256, 256>>>(w_conv1);
    k_conv1_mma<<<dim3(32, 2, BATCH), 256, CONV_SMEM_BYTES>>>(x);
    k_prep<<<(BATCH*CHAN*HWSZ/4 + 255)/256, 256>>>(x, g_bn1, be_bn1);
    k_gemm_mma<<<dim3(BATCH*HH, 4), 256>>>();
    k_final<<<(BATCH*CHAN*HWSZ/4 + 255)/256, 256>>>(out, g_bn2, be_bn2, g_bns, be_bns);
}